// round 15
// baseline (speedup 1.0000x reference)
#include <cuda_runtime.h>
#include <cuda_bf16.h>
#include <cstdint>

#define BB   4
#define HH   16
#define SKK  4096
#define SQQ  4096
#define DD   64
#define NN   32
#define SPLIT_BLK 8
#define SPLIT 32
#define KEYS_PER_BLOCK (SKK / SPLIT_BLK)   // 512
#define CHUNK 32
#define NCHUNK (KEYS_PER_BLOCK / CHUNK)    // 16

typedef unsigned long long u64;

__device__ __forceinline__ float OMEGA() { return 32.0f * 3.14159265358979323846f / 31.0f; }

// Scratch
__device__ float g_part[SPLIT * 64 * 64 * DD];  // [split][hb][f][d] = 33.5 MB
__device__ float g_ab[64 * 64 * DD];            // [hb][f][d]        = 1 MB

// ---- packed f32x2 helpers ----
__device__ __forceinline__ u64 pack2(float lo, float hi) {
    u64 r; asm("mov.b64 %0, {%1, %2};" : "=l"(r) : "f"(lo), "f"(hi)); return r;
}
__device__ __forceinline__ u64 ffma2(u64 a, u64 b, u64 c) {
    u64 d; asm("fma.rn.f32x2 %0, %1, %2, %3;" : "=l"(d) : "l"(a), "l"(b), "l"(c));
    return d;
}

// ============================================================================
// Kernel 1: partial KV = [cos_k^T V ; sin_k^T V], double-buffered.
// grid (8, 64 hb), block 256 = 4 substreams x (2 d-halves x 32 n).
// Warp lanes differ only in n -> V row loads are BROADCAST (no penalty).
// Thread: 1 n x 32 d, acc = 16 u64 cos + 16 u64 sin.
// ============================================================================
__global__ __launch_bounds__(256, 2) void kv_partial(const float* __restrict__ key,
                                                     const float* __restrict__ value) {
    const int sblk = blockIdx.x;
    const int hb = blockIdx.y;
    const int h  = hb >> 2;
    const int b  = hb & 3;
    const int tid = threadIdx.x;
    const int ss = tid >> 6;            // substream 0..3 (8 k each per chunk)
    const int dh = (tid >> 5) & 1;      // d-half (constant within warp)
    const int n  = tid & 31;            // lane = n

    __shared__ float  sv[2][CHUNK][68];     // value rows, padded
    __shared__ float2 scs[2][CHUNK][33];    // {c,s}[k][n], padded

    u64 accC[16], accS[16];
    #pragma unroll
    for (int j = 0; j < 16; j++) { accC[j] = 0ull; accS[j] = 0ull; }

    const int kbase = sblk * KEYS_PER_BLOCK;
    const size_t vrow_base = ((size_t)b * SKK) * (HH * DD) + (size_t)h * DD;
    const size_t krow_base = (size_t)b * SKK * HH + h;

    // staging maps
    const int vk0 = tid >> 4;            // value row (0..15)
    const int vj0 = tid & 15;            // float4 within row
    const int tr  = tid >> 5;            // trig n-group 0..7 -> n = 4*tr..4*tr+3
    const int tk  = tid & 31;            // trig k

    float4 pv0, pv1; float pkey;
    {
        const int kk0 = kbase;
        pv0 = *(reinterpret_cast<const float4*>(
                  value + vrow_base + (size_t)(kk0 + vk0) * (HH * DD)) + vj0);
        pv1 = *(reinterpret_cast<const float4*>(
                  value + vrow_base + (size_t)(kk0 + 16 + vk0) * (HH * DD)) + vj0);
        pkey = key[krow_base + (size_t)(kk0 + tk) * HH];
    }

    for (int c = 0; c < NCHUNK; c++) {
        const int cur = c & 1;

        // fill buf[cur]
        *reinterpret_cast<float4*>(&sv[cur][vk0][vj0 * 4])      = pv0;
        *reinterpret_cast<float4*>(&sv[cur][16 + vk0][vj0 * 4]) = pv1;
        {
            float base = OMEGA() * pkey;
            float s1, c1; sincosf(base, &s1, &c1);
            float sb, cb; sincosf((float)(4 * tr) * base, &sb, &cb);
            #pragma unroll
            for (int j = 0; j < 4; j++) {
                scs[cur][tk][4 * tr + j] = make_float2(cb, sb);
                float cn = cb * c1 - sb * s1;
                float sn = sb * c1 + cb * s1;
                cb = cn; sb = sn;
            }
        }

        // prefetch next chunk
        if (c + 1 < NCHUNK) {
            const int kk0 = kbase + (c + 1) * CHUNK;
            pv0 = *(reinterpret_cast<const float4*>(
                      value + vrow_base + (size_t)(kk0 + vk0) * (HH * DD)) + vj0);
            pv1 = *(reinterpret_cast<const float4*>(
                      value + vrow_base + (size_t)(kk0 + 16 + vk0) * (HH * DD)) + vj0);
            pkey = key[krow_base + (size_t)(kk0 + tk) * HH];
        }

        __syncthreads();

        // compute: this substream's 8 keys
        const int kb = ss * 8;
        #pragma unroll
        for (int kk = 0; kk < 8; kk++) {
            const int k = kb + kk;
            float2 t = scs[cur][k][n];          // lane-spread, conflict-free
            u64 c2 = pack2(t.x, t.x);
            u64 s2 = pack2(t.y, t.y);
            const float* vr = &sv[cur][k][dh * 32];   // BROADCAST across lanes
            #pragma unroll
            for (int j = 0; j < 8; j++) {
                ulonglong2 w = *reinterpret_cast<const ulonglong2*>(vr + 4 * j);
                accC[2 * j]     = ffma2(c2, w.x, accC[2 * j]);
                accC[2 * j + 1] = ffma2(c2, w.y, accC[2 * j + 1]);
                accS[2 * j]     = ffma2(s2, w.x, accS[2 * j]);
                accS[2 * j + 1] = ffma2(s2, w.y, accS[2 * j + 1]);
            }
        }
    }

    // write partials: split index = sblk*4 + ss
    const int sout = sblk * 4 + ss;
    float* base = g_part + ((size_t)(sout * 64 + hb) * 64) * 64;
    float* pc = base + n * 64 + dh * 32;          // f = n (cos)
    float* ps = base + (32 + n) * 64 + dh * 32;   // f = 32+n (sin)
    #pragma unroll
    for (int j = 0; j < 16; j++) {
        *reinterpret_cast<u64*>(pc + 2 * j) = accC[j];
        *reinterpret_cast<u64*>(ps + 2 * j) = accS[j];
    }
}

// ============================================================================
// Kernel 2: reduce 32 split partials and fold amplitudes into g_ab.
// ============================================================================
__global__ __launch_bounds__(256) void kv_combine(const float* __restrict__ ra,
                                                  const float* __restrict__ ia) {
    const int hb = blockIdx.x;
    const int h  = hb >> 2;
    const int tid = threadIdx.x;

    #pragma unroll
    for (int i = 0; i < 8; i++) {
        int idx = i * 256 + tid;
        int n = idx >> 6, d = idx & 63;
        float sc = 0.f, ss = 0.f;
        #pragma unroll 8
        for (int s = 0; s < SPLIT; s++) {
            const float* base = g_part + (size_t)(s * 64 + hb) * 64 * DD;
            sc += base[n * DD + d];
            ss += base[(32 + n) * DD + d];
        }
        float r  = ra[h * NN + n];
        float im = ia[h * NN + n];
        g_ab[((size_t)hb * 64 + n) * DD + d]      = r * sc - im * ss;
        g_ab[((size_t)hb * 64 + 32 + n) * DD + d] = r * ss + im * sc;
    }
}

// ============================================================================
// Kernel 3: out[q][d] = sum_n cos_q*A[n][d] + sin_q*B[n][d].
// grid (32, 64 hb), block 256 = 128 q x 2 d-halves (warp lanes differ in q).
// Trig in REGISTERS (4 rotation chains); AB rows broadcast from smem.
// Epilogue transposed through aliased smem for coalesced stores.
// ============================================================================
__global__ __launch_bounds__(256, 2) void phase2(const float* __restrict__ query,
                                                 float* __restrict__ out) {
    const int qt = blockIdx.x;
    const int hb = blockIdx.y;
    const int h  = hb >> 2;
    const int b  = hb & 3;
    const int tid = threadIdx.x;
    const int q  = tid & 127;
    const int dh = tid >> 7;            // constant within warp
    const int qblk = qt * 128;

    __shared__ __align__(16) float sbuf[128 * 66];   // 33.8 KB
    // phase A view: AB[f][d] = sbuf[f*64 + d]  (first 4096 floats)
    // phase B view: OUT[q][d] = sbuf[q*66 + d]

    // load AB tile: 1024 float4 / 256 threads
    #pragma unroll
    for (int i = 0; i < 4; i++) {
        int idx4 = i * 256 + tid;
        reinterpret_cast<float4*>(sbuf)[idx4] =
            reinterpret_cast<const float4*>(g_ab + (size_t)hb * 64 * DD)[idx4];
    }

    // trig register state: 4 chains, step e^{i*4theta}
    float cc[4], sc[4], c4, s4;
    {
        float qv = query[((size_t)b * SQQ + qblk + q) * HH + h];
        float th = OMEGA() * qv;
        float s1, c1; sincosf(th, &s1, &c1);
        float c2 = c1 * c1 - s1 * s1, s2 = 2.f * c1 * s1;
        float c3 = c2 * c1 - s2 * s1, s3 = s2 * c1 + c2 * s1;
        c4 = c2 * c2 - s2 * s2; s4 = 2.f * c2 * s2;
        cc[0] = 1.f; cc[1] = c1; cc[2] = c2; cc[3] = c3;
        sc[0] = 0.f; sc[1] = s1; sc[2] = s2; sc[3] = s3;
    }
    __syncthreads();

    u64 acc[16];
    #pragma unroll
    for (int j = 0; j < 16; j++) acc[j] = 0ull;

    #pragma unroll
    for (int n = 0; n < NN; n++) {
        const int g = n & 3;
        u64 cq = pack2(cc[g], cc[g]);
        u64 sq = pack2(sc[g], sc[g]);
        const float* ar = sbuf + n * 64 + dh * 32;         // BROADCAST
        #pragma unroll
        for (int j = 0; j < 8; j++) {
            ulonglong2 w = *reinterpret_cast<const ulonglong2*>(ar + 4 * j);
            acc[2 * j]     = ffma2(cq, w.x, acc[2 * j]);
            acc[2 * j + 1] = ffma2(cq, w.y, acc[2 * j + 1]);
        }
        const float* br = sbuf + (32 + n) * 64 + dh * 32;  // BROADCAST
        #pragma unroll
        for (int j = 0; j < 8; j++) {
            ulonglong2 w = *reinterpret_cast<const ulonglong2*>(br + 4 * j);
            acc[2 * j]     = ffma2(sq, w.x, acc[2 * j]);
            acc[2 * j + 1] = ffma2(sq, w.y, acc[2 * j + 1]);
        }
        // rotate chain g by e^{i*4theta}
        float cn = cc[g] * c4 - sc[g] * s4;
        float sn = sc[g] * c4 + cc[g] * s4;
        cc[g] = cn; sc[g] = sn;
    }

    __syncthreads();   // all reads of AB done; sbuf reusable

    // stage output tile: OUT[q][dh*32 .. dh*32+31]
    {
        float* orow = sbuf + q * 66 + dh * 32;
        #pragma unroll
        for (int j = 0; j < 16; j++)
            *reinterpret_cast<u64*>(orow + 2 * j) = acc[j];
    }
    __syncthreads();

    // coalesced global writes: 4096 float2 / 256 threads = 16 each
    #pragma unroll
    for (int i = 0; i < 16; i++) {
        int idx2 = i * 256 + tid;
        int qq = idx2 >> 5, j = idx2 & 31;
        float2 v = *reinterpret_cast<const float2*>(sbuf + qq * 66 + 2 * j);
        float* p = out + (((size_t)b * SQQ + qblk + qq) * HH + h) * DD + 2 * j;
        *reinterpret_cast<float2*>(p) = v;
    }
}

// ============================================================================
extern "C" void kernel_launch(void* const* d_in, const int* in_sizes, int n_in,
                              void* d_out, int out_size) {
    const float* key   = (const float*)d_in[0];  // (B, SK, H)
    const float* value = (const float*)d_in[1];  // (B, SK, H*D)
    const float* query = (const float*)d_in[2];  // (B, SQ, H)
    const float* ra    = (const float*)d_in[3];  // (H,1,1,N)
    const float* ia    = (const float*)d_in[4];  // (H,1,1,N)
    float* out = (float*)d_out;                  // (B, SQ, H*D)

    dim3 g1(SPLIT_BLK, 64);
    kv_partial<<<g1, 256>>>(key, value);
    kv_combine<<<64, 256>>>(ra, ia);
    dim3 g3(SQQ / 128, 64);
    phase2<<<g3, 256>>>(query, out);
}

// round 16
// speedup vs baseline: 1.5417x; 1.5417x over previous
#include <cuda_runtime.h>
#include <cuda_bf16.h>
#include <cstdint>

#define BB   4
#define HH   16
#define SKK  4096
#define SQQ  4096
#define DD   64
#define NN   32
#define SPLIT_BLK 16
#define SPLIT 32
#define KEYS_PER_BLOCK (SKK / SPLIT_BLK)   // 256
#define CHUNK 32
#define NCHUNK (KEYS_PER_BLOCK / CHUNK)    // 8

typedef unsigned long long u64;

__device__ __forceinline__ float OMEGA() { return 32.0f * 3.14159265358979323846f / 31.0f; }

// Scratch
__device__ float g_part[SPLIT * 64 * 64 * DD];  // [split][hb][f][d] = 33.5 MB
__device__ float g_ab[64 * 64 * DD];            // [hb][f][d]        = 1 MB

// ---- packed f32x2 helpers ----
__device__ __forceinline__ u64 pack2(float lo, float hi) {
    u64 r; asm("mov.b64 %0, {%1, %2};" : "=l"(r) : "f"(lo), "f"(hi)); return r;
}
__device__ __forceinline__ void unpack2(u64 v, float& lo, float& hi) {
    asm("mov.b64 {%0, %1}, %2;" : "=f"(lo), "=f"(hi) : "l"(v));
}
__device__ __forceinline__ u64 ffma2(u64 a, u64 b, u64 c) {
    u64 d; asm("fma.rn.f32x2 %0, %1, %2, %3;" : "=l"(d) : "l"(a), "l"(b), "l"(c));
    return d;
}
__device__ __forceinline__ u64 lds64(const float* p) {
    return *reinterpret_cast<const u64*>(p);
}

// ============================================================================
// Kernel 1: partial KV = [cos_k^T V ; sin_k^T V], double-buffered pipeline.
// grid: (16, 64 hb), block 256 = 2 substreams x 128 threads.
// Thread tile: 2 n (n0, n0+16) x 8 d. One __syncthreads per 32-key chunk.
// ============================================================================
__global__ __launch_bounds__(256, 3) void kv_partial(const float* __restrict__ key,
                                                     const float* __restrict__ value) {
    const int sblk = blockIdx.x;
    const int hb = blockIdx.y;
    const int h  = hb >> 2;
    const int b  = hb & 3;
    const int tid = threadIdx.x;
    const int ss = tid >> 7;           // substream 0/1 (16 k each per chunk)
    const int t  = tid & 127;
    const int n0 = t >> 3;             // 0..15
    const int dg = t & 7;
    const int d0 = dg * 4;

    __shared__ float  sv[2][CHUNK][68];     // value rows, padded (2 x 8.7 KB)
    __shared__ float2 scs[2][NN][34];       // {c,s}[n][k], k-padded (2 x 8.5 KB)

    u64 aC0[4] = {}, aS0[4] = {}, aC1[4] = {}, aS1[4] = {};

    const int kbase = sblk * KEYS_PER_BLOCK;
    const size_t vrow_base = ((size_t)b * SKK) * (HH * DD) + (size_t)h * DD;
    const size_t krow_base = (size_t)b * SKK * HH + h;

    // staging maps
    const int vk0 = tid >> 4;            // value row (0..15)
    const int vj0 = tid & 15;            // float4 within row
    const int tr  = tid >> 5;            // trig n-group 0..7 -> n = 4*tr..4*tr+3
    const int tk  = tid & 31;            // trig k

    float4 pv0, pv1; float pkey;
    {   // prefetch chunk 0
        const int kk0 = kbase;
        pv0 = *(reinterpret_cast<const float4*>(
                  value + vrow_base + (size_t)(kk0 + vk0) * (HH * DD)) + vj0);
        pv1 = *(reinterpret_cast<const float4*>(
                  value + vrow_base + (size_t)(kk0 + 16 + vk0) * (HH * DD)) + vj0);
        pkey = key[krow_base + (size_t)(kk0 + tk) * HH];
    }

    for (int c = 0; c < NCHUNK; c++) {
        const int cur = c & 1;

        // ---- fill buf[cur] from prefetched regs ----
        *reinterpret_cast<float4*>(&sv[cur][vk0][vj0 * 4])      = pv0;
        *reinterpret_cast<float4*>(&sv[cur][16 + vk0][vj0 * 4]) = pv1;
        {
            float base = OMEGA() * pkey;
            float s1, c1; sincosf(base, &s1, &c1);
            float sb, cb; sincosf((float)(4 * tr) * base, &sb, &cb);
            #pragma unroll
            for (int j = 0; j < 4; j++) {
                scs[cur][4 * tr + j][tk] = make_float2(cb, sb);
                float cn = cb * c1 - sb * s1;
                float sn = sb * c1 + cb * s1;
                cb = cn; sb = sn;
            }
        }

        // ---- prefetch chunk c+1 (LDG latency hidden by compute below) ----
        if (c + 1 < NCHUNK) {
            const int kk0 = kbase + (c + 1) * CHUNK;
            pv0 = *(reinterpret_cast<const float4*>(
                      value + vrow_base + (size_t)(kk0 + vk0) * (HH * DD)) + vj0);
            pv1 = *(reinterpret_cast<const float4*>(
                      value + vrow_base + (size_t)(kk0 + 16 + vk0) * (HH * DD)) + vj0);
            pkey = key[krow_base + (size_t)(kk0 + tk) * HH];
        }

        __syncthreads();   // buf[cur] ready; prior compute (other buffer) done

        // ---- compute on buf[cur]: this substream's 16 keys, in k-pairs ----
        const int kb = ss * 16;
        #pragma unroll
        for (int kk = 0; kk < 16; kk += 2) {
            const int k = kb + kk;
            float4 T0 = *reinterpret_cast<const float4*>(&scs[cur][n0][k]);
            float4 T1 = *reinterpret_cast<const float4*>(&scs[cur][n0 + 16][k]);

            #pragma unroll
            for (int u = 0; u < 2; u++) {
                const float* vrow = &sv[cur][k + u][0];
                ulonglong2 Va = *reinterpret_cast<const ulonglong2*>(vrow + d0);
                ulonglong2 Vb = *reinterpret_cast<const ulonglong2*>(vrow + d0 + 32);
                float cf0 = u ? T0.z : T0.x, sf0 = u ? T0.w : T0.y;
                float cf1 = u ? T1.z : T1.x, sf1 = u ? T1.w : T1.y;
                u64 c0 = pack2(cf0, cf0), s0 = pack2(sf0, sf0);
                u64 c1 = pack2(cf1, cf1), s1 = pack2(sf1, sf1);
                aC0[0] = ffma2(c0, Va.x, aC0[0]); aC0[1] = ffma2(c0, Va.y, aC0[1]);
                aC0[2] = ffma2(c0, Vb.x, aC0[2]); aC0[3] = ffma2(c0, Vb.y, aC0[3]);
                aS0[0] = ffma2(s0, Va.x, aS0[0]); aS0[1] = ffma2(s0, Va.y, aS0[1]);
                aS0[2] = ffma2(s0, Vb.x, aS0[2]); aS0[3] = ffma2(s0, Vb.y, aS0[3]);
                aC1[0] = ffma2(c1, Va.x, aC1[0]); aC1[1] = ffma2(c1, Va.y, aC1[1]);
                aC1[2] = ffma2(c1, Vb.x, aC1[2]); aC1[3] = ffma2(c1, Vb.y, aC1[3]);
                aS1[0] = ffma2(s1, Va.x, aS1[0]); aS1[1] = ffma2(s1, Va.y, aS1[1]);
                aS1[2] = ffma2(s1, Vb.x, aS1[2]); aS1[3] = ffma2(s1, Vb.y, aS1[3]);
            }
        }
    }

    // write partials: split index = sblk*2 + ss
    const int sout = sblk * 2 + ss;
    float* base = g_part + (size_t)(sout * 64 + hb) * 64 * DD;
    float o[8];
    u64* accs[4] = {aC0, aC1, aS0, aS1};
    const int frow[4] = {n0, n0 + 16, 32 + n0, 48 + n0};
    #pragma unroll
    for (int g = 0; g < 4; g++) {
        #pragma unroll
        for (int j = 0; j < 4; j++) unpack2(accs[g][j], o[2 * j], o[2 * j + 1]);
        float* p = base + frow[g] * DD + d0;
        *reinterpret_cast<float4*>(p)      = make_float4(o[0], o[1], o[2], o[3]);
        *reinterpret_cast<float4*>(p + 32) = make_float4(o[4], o[5], o[6], o[7]);
    }
}

// ============================================================================
// Kernel 2: reduce split partials and fold amplitudes.
// ============================================================================
__global__ __launch_bounds__(256) void kv_combine(const float* __restrict__ ra,
                                                  const float* __restrict__ ia) {
    const int hb = blockIdx.x;
    const int h  = hb >> 2;
    const int tid = threadIdx.x;

    #pragma unroll
    for (int i = 0; i < 8; i++) {
        int idx = i * 256 + tid;
        int n = idx >> 6, d = idx & 63;
        float sc = 0.f, ss = 0.f;
        #pragma unroll 8
        for (int s = 0; s < SPLIT; s++) {
            const float* base = g_part + (size_t)(s * 64 + hb) * 64 * DD;
            sc += base[n * DD + d];
            ss += base[(32 + n) * DD + d];
        }
        float r  = ra[h * NN + n];
        float im = ia[h * NN + n];
        g_ab[((size_t)hb * 64 + n) * DD + d]      = r * sc - im * ss;
        g_ab[((size_t)hb * 64 + 32 + n) * DD + d] = r * ss + im * sc;
    }
}

// ============================================================================
// Kernel 3: out[q][d] = sum_n cos_q*A[n][d] + sin_q*B[n][d].
// grid: (SQ/128, 64 hb), block 128. Thread tile: 8 q x 8 d.
// ============================================================================
__global__ __launch_bounds__(128, 4) void phase2(const float* __restrict__ query,
                                                 float* __restrict__ out) {
    const int qt = blockIdx.x;
    const int hb = blockIdx.y;
    const int h  = hb >> 2;
    const int b  = hb & 3;
    const int tid = threadIdx.x;
    const int qblk = qt * 128;

    __shared__ float sAB[64][64];        // 16 KB
    __shared__ float scost[NN][128];     // 16 KB
    __shared__ float ssint[NN][128];     // 16 KB  (total exactly 48 KB)

    #pragma unroll
    for (int i = 0; i < 8; i++) {
        int idx4 = i * 128 + tid;
        reinterpret_cast<float4*>(&sAB[0][0])[idx4] =
            reinterpret_cast<const float4*>(g_ab + (size_t)hb * 64 * DD)[idx4];
    }
    // trig: one thread per q; 4 independent rotation chains (step e^{i*4theta})
    {
        int q = tid;
        float qv = query[((size_t)b * SQQ + qblk + q) * HH + h];
        float th = OMEGA() * qv;
        float s1, c1; sincosf(th, &s1, &c1);
        float c2 = c1 * c1 - s1 * s1, s2 = 2.f * c1 * s1;
        float c3 = c2 * c1 - s2 * s1, s3 = s2 * c1 + c2 * s1;
        float c4 = c2 * c2 - s2 * s2, s4 = 2.f * c2 * s2;
        float cc[4] = {1.f, c1, c2, c3};
        float sc[4] = {0.f, s1, s2, s3};
        #pragma unroll
        for (int m = 0; m < 8; m++) {
            #pragma unroll
            for (int g = 0; g < 4; g++) {
                scost[4 * m + g][q] = cc[g];
                ssint[4 * m + g][q] = sc[g];
                float cn = cc[g] * c4 - sc[g] * s4;
                float sn = sc[g] * c4 + cc[g] * s4;
                cc[g] = cn; sc[g] = sn;
            }
        }
    }
    __syncthreads();

    const int qg = tid >> 3;   const int q0 = qg * 8;
    const int dg = tid & 7;    const int d0 = dg * 4;

    u64 acc[8][4];
    #pragma unroll
    for (int qi = 0; qi < 8; qi++)
        #pragma unroll
        for (int j = 0; j < 4; j++) acc[qi][j] = 0ull;

    #pragma unroll 2
    for (int n = 0; n < NN; n++) {
        const float* arow = &sAB[n][0];
        const float* brow = &sAB[32 + n][0];
        ulonglong2 A0 = *reinterpret_cast<const ulonglong2*>(arow + d0);
        ulonglong2 A1 = *reinterpret_cast<const ulonglong2*>(arow + d0 + 32);
        ulonglong2 B0 = *reinterpret_cast<const ulonglong2*>(brow + d0);
        ulonglong2 B1 = *reinterpret_cast<const ulonglong2*>(brow + d0 + 32);
        float4 cqa = *reinterpret_cast<const float4*>(&scost[n][q0]);
        float4 cqb = *reinterpret_cast<const float4*>(&scost[n][q0 + 4]);
        float4 sqa = *reinterpret_cast<const float4*>(&ssint[n][q0]);
        float4 sqb = *reinterpret_cast<const float4*>(&ssint[n][q0 + 4]);
        const float cf[8] = {cqa.x, cqa.y, cqa.z, cqa.w, cqb.x, cqb.y, cqb.z, cqb.w};
        const float sf[8] = {sqa.x, sqa.y, sqa.z, sqa.w, sqb.x, sqb.y, sqb.z, sqb.w};
        #pragma unroll
        for (int qi = 0; qi < 8; qi++) {
            u64 cq = pack2(cf[qi], cf[qi]);
            u64 sq = pack2(sf[qi], sf[qi]);
            acc[qi][0] = ffma2(cq, A0.x, acc[qi][0]);
            acc[qi][1] = ffma2(cq, A0.y, acc[qi][1]);
            acc[qi][2] = ffma2(cq, A1.x, acc[qi][2]);
            acc[qi][3] = ffma2(cq, A1.y, acc[qi][3]);
            acc[qi][0] = ffma2(sq, B0.x, acc[qi][0]);
            acc[qi][1] = ffma2(sq, B0.y, acc[qi][1]);
            acc[qi][2] = ffma2(sq, B1.x, acc[qi][2]);
            acc[qi][3] = ffma2(sq, B1.y, acc[qi][3]);
        }
    }

    #pragma unroll
    for (int qi = 0; qi < 8; qi++) {
        float o[8];
        #pragma unroll
        for (int j = 0; j < 4; j++) unpack2(acc[qi][j], o[2*j], o[2*j+1]);
        float* p = out + (((size_t)b * SQQ + qblk + q0 + qi) * HH + h) * DD + d0;
        *reinterpret_cast<float4*>(p)      = make_float4(o[0], o[1], o[2], o[3]);
        *reinterpret_cast<float4*>(p + 32) = make_float4(o[4], o[5], o[6], o[7]);
    }
}

// ============================================================================
extern "C" void kernel_launch(void* const* d_in, const int* in_sizes, int n_in,
                              void* d_out, int out_size) {
    const float* key   = (const float*)d_in[0];  // (B, SK, H)
    const float* value = (const float*)d_in[1];  // (B, SK, H*D)
    const float* query = (const float*)d_in[2];  // (B, SQ, H)
    const float* ra    = (const float*)d_in[3];  // (H,1,1,N)
    const float* ia    = (const float*)d_in[4];  // (H,1,1,N)
    float* out = (float*)d_out;                  // (B, SQ, H*D)

    dim3 g1(SPLIT_BLK, 64);
    kv_partial<<<g1, 256>>>(key, value);
    kv_combine<<<64, 256>>>(ra, ia);
    dim3 g3(SQQ / 128, 64);
    phase2<<<g3, 128>>>(query, out);
}

// round 17
// speedup vs baseline: 1.7107x; 1.1096x over previous
#include <cuda_runtime.h>
#include <cuda_bf16.h>
#include <cstdint>

#define BB   4
#define HH   16
#define SKK  4096
#define SQQ  4096
#define DD   64
#define NN   32
#define SPLIT_BLK 16
#define SPLIT 16
#define KEYS_PER_BLOCK (SKK / SPLIT_BLK)   // 256
#define CHUNK 32
#define NCHUNK (KEYS_PER_BLOCK / CHUNK)    // 8

typedef unsigned long long u64;

__device__ __forceinline__ float OMEGA() { return 32.0f * 3.14159265358979323846f / 31.0f; }

// Scratch
__device__ float g_part[SPLIT * 64 * 64 * DD];  // [split][hb][f][d] = 16.8 MB
__device__ float g_ab[64 * 64 * DD];            // [hb][f][d]        = 1 MB

// ---- packed f32x2 helpers ----
__device__ __forceinline__ u64 pack2(float lo, float hi) {
    u64 r; asm("mov.b64 %0, {%1, %2};" : "=l"(r) : "f"(lo), "f"(hi)); return r;
}
__device__ __forceinline__ void unpack2(u64 v, float& lo, float& hi) {
    asm("mov.b64 {%0, %1}, %2;" : "=f"(lo), "=f"(hi) : "l"(v));
}
__device__ __forceinline__ u64 ffma2(u64 a, u64 b, u64 c) {
    u64 d; asm("fma.rn.f32x2 %0, %1, %2, %3;" : "=l"(d) : "l"(a), "l"(b), "l"(c));
    return d;
}

// ============================================================================
// Kernel 1: partial KV = [cos_k^T V ; sin_k^T V], double-buffered pipeline.
// grid: (16, 64 hb), block 256 = 2 substreams x 128 threads.
// Thread tile: 2 n (n0, n0+16) x 8 d. In-block substream merge at the end.
// ============================================================================
__global__ __launch_bounds__(256, 3) void kv_partial(const float* __restrict__ key,
                                                     const float* __restrict__ value) {
    const int sblk = blockIdx.x;
    const int hb = blockIdx.y;
    const int h  = hb >> 2;
    const int b  = hb & 3;
    const int tid = threadIdx.x;
    const int ss = tid >> 7;           // substream 0/1 (16 k each per chunk)
    const int t  = tid & 127;
    const int n0 = t >> 3;             // 0..15
    const int dg = t & 7;
    const int d0 = dg * 4;

    __shared__ float  sv[2][CHUNK][68];     // value rows; reused as merge buffer
    __shared__ float2 scs[2][NN][34];       // {c,s}[n][k]

    u64 aC0[4] = {}, aS0[4] = {}, aC1[4] = {}, aS1[4] = {};

    const int kbase = sblk * KEYS_PER_BLOCK;
    const size_t vrow_base = ((size_t)b * SKK) * (HH * DD) + (size_t)h * DD;
    const size_t krow_base = (size_t)b * SKK * HH + h;

    // staging maps
    const int vk0 = tid >> 4;            // value row (0..15)
    const int vj0 = tid & 15;            // float4 within row
    const int tr  = tid >> 5;            // trig n-group 0..7 -> n = 4*tr..4*tr+3
    const int tk  = tid & 31;            // trig k

    float4 pv0, pv1; float pkey;
    {   // prefetch chunk 0
        const int kk0 = kbase;
        pv0 = *(reinterpret_cast<const float4*>(
                  value + vrow_base + (size_t)(kk0 + vk0) * (HH * DD)) + vj0);
        pv1 = *(reinterpret_cast<const float4*>(
                  value + vrow_base + (size_t)(kk0 + 16 + vk0) * (HH * DD)) + vj0);
        pkey = key[krow_base + (size_t)(kk0 + tk) * HH];
    }

    for (int c = 0; c < NCHUNK; c++) {
        const int cur = c & 1;

        // fill buf[cur]
        *reinterpret_cast<float4*>(&sv[cur][vk0][vj0 * 4])      = pv0;
        *reinterpret_cast<float4*>(&sv[cur][16 + vk0][vj0 * 4]) = pv1;
        {
            float base = OMEGA() * pkey;
            float s1, c1; sincosf(base, &s1, &c1);
            float sb, cb; sincosf((float)(4 * tr) * base, &sb, &cb);
            #pragma unroll
            for (int j = 0; j < 4; j++) {
                scs[cur][4 * tr + j][tk] = make_float2(cb, sb);
                float cn = cb * c1 - sb * s1;
                float sn = sb * c1 + cb * s1;
                cb = cn; sb = sn;
            }
        }

        // prefetch chunk c+1
        if (c + 1 < NCHUNK) {
            const int kk0 = kbase + (c + 1) * CHUNK;
            pv0 = *(reinterpret_cast<const float4*>(
                      value + vrow_base + (size_t)(kk0 + vk0) * (HH * DD)) + vj0);
            pv1 = *(reinterpret_cast<const float4*>(
                      value + vrow_base + (size_t)(kk0 + 16 + vk0) * (HH * DD)) + vj0);
            pkey = key[krow_base + (size_t)(kk0 + tk) * HH];
        }

        __syncthreads();

        // compute on buf[cur]
        const int kb = ss * 16;
        #pragma unroll
        for (int kk = 0; kk < 16; kk += 2) {
            const int k = kb + kk;
            float4 T0 = *reinterpret_cast<const float4*>(&scs[cur][n0][k]);
            float4 T1 = *reinterpret_cast<const float4*>(&scs[cur][n0 + 16][k]);

            #pragma unroll
            for (int u = 0; u < 2; u++) {
                const float* vrow = &sv[cur][k + u][0];
                ulonglong2 Va = *reinterpret_cast<const ulonglong2*>(vrow + d0);
                ulonglong2 Vb = *reinterpret_cast<const ulonglong2*>(vrow + d0 + 32);
                float cf0 = u ? T0.z : T0.x, sf0 = u ? T0.w : T0.y;
                float cf1 = u ? T1.z : T1.x, sf1 = u ? T1.w : T1.y;
                u64 c0 = pack2(cf0, cf0), s0 = pack2(sf0, sf0);
                u64 c1 = pack2(cf1, cf1), s1 = pack2(sf1, sf1);
                aC0[0] = ffma2(c0, Va.x, aC0[0]); aC0[1] = ffma2(c0, Va.y, aC0[1]);
                aC0[2] = ffma2(c0, Vb.x, aC0[2]); aC0[3] = ffma2(c0, Vb.y, aC0[3]);
                aS0[0] = ffma2(s0, Va.x, aS0[0]); aS0[1] = ffma2(s0, Va.y, aS0[1]);
                aS0[2] = ffma2(s0, Vb.x, aS0[2]); aS0[3] = ffma2(s0, Vb.y, aS0[3]);
                aC1[0] = ffma2(c1, Va.x, aC1[0]); aC1[1] = ffma2(c1, Va.y, aC1[1]);
                aC1[2] = ffma2(c1, Vb.x, aC1[2]); aC1[3] = ffma2(c1, Vb.y, aC1[3]);
                aS1[0] = ffma2(s1, Va.x, aS1[0]); aS1[1] = ffma2(s1, Va.y, aS1[1]);
                aS1[2] = ffma2(s1, Vb.x, aS1[2]); aS1[3] = ffma2(s1, Vb.y, aS1[3]);
            }
        }
    }

    // ---- in-block substream merge: ss1 -> smem, ss0 adds and writes ----
    __syncthreads();                       // all compute reads of smem done
    float* red = &sv[0][0][0];             // 4096-float merge buffer
    u64* accs[4] = {aC0, aC1, aS0, aS1};
    const int frow[4] = {n0, n0 + 16, 32 + n0, 48 + n0};

    if (ss == 1) {
        #pragma unroll
        for (int g = 0; g < 4; g++) {
            float o[8];
            #pragma unroll
            for (int j = 0; j < 4; j++) unpack2(accs[g][j], o[2*j], o[2*j+1]);
            float* p = red + frow[g] * 64 + d0;
            *reinterpret_cast<float4*>(p)      = make_float4(o[0], o[1], o[2], o[3]);
            *reinterpret_cast<float4*>(p + 32) = make_float4(o[4], o[5], o[6], o[7]);
        }
    }
    __syncthreads();

    if (ss == 0) {
        float* base = g_part + (size_t)(sblk * 64 + hb) * 64 * DD;
        #pragma unroll
        for (int g = 0; g < 4; g++) {
            float o[8];
            #pragma unroll
            for (int j = 0; j < 4; j++) unpack2(accs[g][j], o[2*j], o[2*j+1]);
            const float* r = red + frow[g] * 64 + d0;
            float4 r0 = *reinterpret_cast<const float4*>(r);
            float4 r1 = *reinterpret_cast<const float4*>(r + 32);
            float* p = base + frow[g] * DD + d0;
            *reinterpret_cast<float4*>(p) =
                make_float4(o[0] + r0.x, o[1] + r0.y, o[2] + r0.z, o[3] + r0.w);
            *reinterpret_cast<float4*>(p + 32) =
                make_float4(o[4] + r1.x, o[5] + r1.y, o[6] + r1.z, o[7] + r1.w);
        }
    }
}

// ============================================================================
// Kernel 2: reduce split partials and fold amplitudes.
// ============================================================================
__global__ __launch_bounds__(256) void kv_combine(const float* __restrict__ ra,
                                                  const float* __restrict__ ia) {
    const int hb = blockIdx.x;
    const int h  = hb >> 2;
    const int tid = threadIdx.x;

    #pragma unroll
    for (int i = 0; i < 8; i++) {
        int idx = i * 256 + tid;
        int n = idx >> 6, d = idx & 63;
        float sc = 0.f, ss = 0.f;
        #pragma unroll
        for (int s = 0; s < SPLIT; s++) {
            const float* base = g_part + (size_t)(s * 64 + hb) * 64 * DD;
            sc += base[n * DD + d];
            ss += base[(32 + n) * DD + d];
        }
        float r  = ra[h * NN + n];
        float im = ia[h * NN + n];
        g_ab[((size_t)hb * 64 + n) * DD + d]      = r * sc - im * ss;
        g_ab[((size_t)hb * 64 + 32 + n) * DD + d] = r * ss + im * sc;
    }
}

// ============================================================================
// Kernel 3: out[q][d] = sum_n cos_q*A[n][d] + sin_q*B[n][d].
// grid: (SQ/64, 64 hb), block 128. Thread tile: 4 q x 8 d. 32 KB smem.
// ============================================================================
__global__ __launch_bounds__(128, 4) void phase2(const float* __restrict__ query,
                                                 float* __restrict__ out) {
    const int qt = blockIdx.x;
    const int hb = blockIdx.y;
    const int h  = hb >> 2;
    const int b  = hb & 3;
    const int tid = threadIdx.x;
    const int qblk = qt * 64;

    __shared__ float sAB[64][64];        // 16 KB
    __shared__ float scost[NN][64];      // 8 KB
    __shared__ float ssint[NN][64];      // 8 KB

    #pragma unroll
    for (int i = 0; i < 8; i++) {
        int idx4 = i * 128 + tid;
        reinterpret_cast<float4*>(&sAB[0][0])[idx4] =
            reinterpret_cast<const float4*>(g_ab + (size_t)hb * 64 * DD)[idx4];
    }
    // trig: threads 0..63 own one q each; 4 rotation chains (step e^{i*4theta})
    if (tid < 64) {
        int q = tid;
        float qv = query[((size_t)b * SQQ + qblk + q) * HH + h];
        float th = OMEGA() * qv;
        float s1, c1; sincosf(th, &s1, &c1);
        float c2 = c1 * c1 - s1 * s1, s2 = 2.f * c1 * s1;
        float c3 = c2 * c1 - s2 * s1, s3 = s2 * c1 + c2 * s1;
        float c4 = c2 * c2 - s2 * s2, s4 = 2.f * c2 * s2;
        float cc[4] = {1.f, c1, c2, c3};
        float sc[4] = {0.f, s1, s2, s3};
        #pragma unroll
        for (int m = 0; m < 8; m++) {
            #pragma unroll
            for (int g = 0; g < 4; g++) {
                scost[4 * m + g][q] = cc[g];
                ssint[4 * m + g][q] = sc[g];
                float cn = cc[g] * c4 - sc[g] * s4;
                float sn = sc[g] * c4 + cc[g] * s4;
                cc[g] = cn; sc[g] = sn;
            }
        }
    }
    __syncthreads();

    const int qg = tid >> 3;   const int q0 = qg * 4;   // 4 q
    const int dg = tid & 7;    const int d0 = dg * 4;   // 8 d (two halves)

    u64 acc[4][4];
    #pragma unroll
    for (int qi = 0; qi < 4; qi++)
        #pragma unroll
        for (int j = 0; j < 4; j++) acc[qi][j] = 0ull;

    #pragma unroll 4
    for (int n = 0; n < NN; n++) {
        const float* arow = &sAB[n][0];
        const float* brow = &sAB[32 + n][0];
        ulonglong2 A0 = *reinterpret_cast<const ulonglong2*>(arow + d0);
        ulonglong2 A1 = *reinterpret_cast<const ulonglong2*>(arow + d0 + 32);
        ulonglong2 B0 = *reinterpret_cast<const ulonglong2*>(brow + d0);
        ulonglong2 B1 = *reinterpret_cast<const ulonglong2*>(brow + d0 + 32);
        float4 cq4 = *reinterpret_cast<const float4*>(&scost[n][q0]);
        float4 sq4 = *reinterpret_cast<const float4*>(&ssint[n][q0]);
        const float cf[4] = {cq4.x, cq4.y, cq4.z, cq4.w};
        const float sf[4] = {sq4.x, sq4.y, sq4.z, sq4.w};
        #pragma unroll
        for (int qi = 0; qi < 4; qi++) {
            u64 cq = pack2(cf[qi], cf[qi]);
            u64 sq = pack2(sf[qi], sf[qi]);
            acc[qi][0] = ffma2(cq, A0.x, acc[qi][0]);
            acc[qi][1] = ffma2(cq, A0.y, acc[qi][1]);
            acc[qi][2] = ffma2(cq, A1.x, acc[qi][2]);
            acc[qi][3] = ffma2(cq, A1.y, acc[qi][3]);
            acc[qi][0] = ffma2(sq, B0.x, acc[qi][0]);
            acc[qi][1] = ffma2(sq, B0.y, acc[qi][1]);
            acc[qi][2] = ffma2(sq, B1.x, acc[qi][2]);
            acc[qi][3] = ffma2(sq, B1.y, acc[qi][3]);
        }
    }

    #pragma unroll
    for (int qi = 0; qi < 4; qi++) {
        float o[8];
        #pragma unroll
        for (int j = 0; j < 4; j++) unpack2(acc[qi][j], o[2*j], o[2*j+1]);
        float* p = out + (((size_t)b * SQQ + qblk + q0 + qi) * HH + h) * DD + d0;
        *reinterpret_cast<float4*>(p)      = make_float4(o[0], o[1], o[2], o[3]);
        *reinterpret_cast<float4*>(p + 32) = make_float4(o[4], o[5], o[6], o[7]);
    }
}

// ============================================================================
extern "C" void kernel_launch(void* const* d_in, const int* in_sizes, int n_in,
                              void* d_out, int out_size) {
    const float* key   = (const float*)d_in[0];  // (B, SK, H)
    const float* value = (const float*)d_in[1];  // (B, SK, H*D)
    const float* query = (const float*)d_in[2];  // (B, SQ, H)
    const float* ra    = (const float*)d_in[3];  // (H,1,1,N)
    const float* ia    = (const float*)d_in[4];  // (H,1,1,N)
    float* out = (float*)d_out;                  // (B, SQ, H*D)

    dim3 g1(SPLIT_BLK, 64);
    kv_partial<<<g1, 256>>>(key, value);
    kv_combine<<<64, 256>>>(ra, ia);
    dim3 g3(SQQ / 64, 64);
    phase2<<<g3, 128>>>(query, out);
}